// round 1
// baseline (speedup 1.0000x reference)
#include <cuda_runtime.h>

#define NT 256
#define PITCH 193

// SMEM layout (floats)
#define OFF_A   0          // 64x192 pitch 193: X, then Y, then merge2 output T
#define OFF_Q   12352      // full Q (scaled)
#define OFF_M   24704      // merge1 accumulator
#define OFF_KH  37056      // 64x32 pitch 33
#define OFF_VH  39168
#define OFF_S   41280      // 64x64 pitch 65
#define OFF_OH  45440      // 64x32 pitch 33
#define OFF_MSK 47552      // 64x64 pitch 65
#define OFF_WST 51712      // 6336 floats: per-head W stage (pitch 33 or 198)
#define SMEM_FLOATS 58048  // 232192 bytes
#define OFF_WTF OFF_KH     // final-phase Wt stage overlay (192x65 = 12480 floats)

__device__ float g_bias[2 * 6 * 64 * 64];

__global__ void bias_pre_kernel(const float* __restrict__ rpb_x,
                                const float* __restrict__ rpb_y,
                                const int* __restrict__ rel_idx) {
    int i = blockIdx.x * blockDim.x + threadIdx.x;
    if (i >= 2 * 6 * 4096) return;
    int br = i / (6 * 4096);
    int h  = (i / 4096) % 6;
    int nm = i & 4095;
    const float* tab = br ? rpb_y : rpb_x;
    g_bias[i] = tab[rel_idx[nm] * 6 + h];
}

__global__ void __launch_bounds__(NT, 1) fused_attn_kernel(
    const float* __restrict__ x, const float* __restrict__ y,
    const float* __restrict__ mask_x, const float* __restrict__ mask_y,
    const float* __restrict__ qkv_w, const float* __restrict__ qkv_b,
    const float* __restrict__ kv_w, const float* __restrict__ kv_b,
    const float* __restrict__ merge1_w, const float* __restrict__ merge1_b,
    const float* __restrict__ merge2_w, const float* __restrict__ merge2_b,
    const float* __restrict__ proj_w, const float* __restrict__ proj_b,
    float* __restrict__ out)
{
    extern __shared__ float sm[];
    const int t = threadIdx.x;
    const int w = blockIdx.x;
    const int tr = t >> 4, tc = t & 15;
    const float scale = 0.17677669529663687f;  // 32^-0.5

    // ---- load X; init M with merge1_b ----
    {
        const float* xp = x + (size_t)w * 12288;
        for (int i = t; i < 12288; i += NT) {
            int n = i / 192, c = i - n * 192;
            sm[OFF_A + n * PITCH + c] = xp[i];
            sm[OFF_M + n * PITCH + c] = merge1_b[c];
        }
    }
    __syncthreads();

    // ---- full Q = scale*(X @ Wq^T + bq), per-head slices ----
    for (int h = 0; h < 6; ++h) {
        for (int i = t; i < 6144; i += NT) {
            int d = i / 192, c = i - d * 192;
            sm[OFF_WST + c * 33 + d] = qkv_w[(h * 32 + d) * 192 + c];
        }
        __syncthreads();
        {
            const int n0 = tr * 4, d0 = tc * 2;
            float b0 = qkv_b[h * 32 + d0], b1 = qkv_b[h * 32 + d0 + 1];
            float acc[4][2];
            #pragma unroll
            for (int i = 0; i < 4; i++) { acc[i][0] = b0; acc[i][1] = b1; }
            #pragma unroll 4
            for (int c = 0; c < 192; c++) {
                float w0 = sm[OFF_WST + c * 33 + d0];
                float w1 = sm[OFF_WST + c * 33 + d0 + 1];
                #pragma unroll
                for (int i = 0; i < 4; i++) {
                    float av = sm[OFF_A + (n0 + i) * PITCH + c];
                    acc[i][0] += av * w0;
                    acc[i][1] += av * w1;
                }
            }
            #pragma unroll
            for (int i = 0; i < 4; i++) {
                sm[OFF_Q + (n0 + i) * PITCH + h * 32 + d0]     = acc[i][0] * scale;
                sm[OFF_Q + (n0 + i) * PITCH + h * 32 + d0 + 1] = acc[i][1] * scale;
            }
        }
        __syncthreads();
    }

    // ---- two branches: self (K,V from X via qkv_w) / cross (K,V from Y via kv_w) ----
    for (int br = 0; br < 2; ++br) {
        if (br == 1) {
            const float* yp = y + (size_t)w * 12288;
            for (int i = t; i < 12288; i += NT) {
                int n = i / 192, c = i - n * 192;
                sm[OFF_A + n * PITCH + c] = yp[i];
            }
        }
        {
            const float* mk = (br ? mask_y : mask_x) + (size_t)(w & 1023) * 4096;
            for (int i = t; i < 4096; i += NT)
                sm[OFF_MSK + (i >> 6) * 65 + (i & 63)] = mk[i];
        }
        __syncthreads();

        const float* Wsrc = br ? kv_w : qkv_w;
        const float* Bsrc = br ? kv_b : qkv_b;
        const int krow0 = br ? 0 : 192;
        const int vrow0 = br ? 192 : 384;

        for (int h = 0; h < 6; ++h) {
            // ---- K_h then V_h ----
            for (int pass = 0; pass < 2; ++pass) {
                const int row0 = (pass ? vrow0 : krow0) + h * 32;
                const int dst = pass ? OFF_VH : OFF_KH;
                for (int i = t; i < 6144; i += NT) {
                    int d = i / 192, c = i - d * 192;
                    sm[OFF_WST + c * 33 + d] = Wsrc[(row0 + d) * 192 + c];
                }
                __syncthreads();
                {
                    const int n0 = tr * 4, d0 = tc * 2;
                    float b0 = Bsrc[row0 + d0], b1 = Bsrc[row0 + d0 + 1];
                    float acc[4][2];
                    #pragma unroll
                    for (int i = 0; i < 4; i++) { acc[i][0] = b0; acc[i][1] = b1; }
                    #pragma unroll 4
                    for (int c = 0; c < 192; c++) {
                        float w0 = sm[OFF_WST + c * 33 + d0];
                        float w1 = sm[OFF_WST + c * 33 + d0 + 1];
                        #pragma unroll
                        for (int i = 0; i < 4; i++) {
                            float av = sm[OFF_A + (n0 + i) * PITCH + c];
                            acc[i][0] += av * w0;
                            acc[i][1] += av * w1;
                        }
                    }
                    #pragma unroll
                    for (int i = 0; i < 4; i++) {
                        sm[dst + (n0 + i) * 33 + d0]     = acc[i][0];
                        sm[dst + (n0 + i) * 33 + d0 + 1] = acc[i][1];
                    }
                }
                __syncthreads();
            }

            // ---- S = Q_h K_h^T + bias + mask ----
            {
                const int n0 = tr * 4, m0 = tc * 4;
                float acc[4][4];
                #pragma unroll
                for (int i = 0; i < 4; i++)
                    #pragma unroll
                    for (int j = 0; j < 4; j++) acc[i][j] = 0.f;
                #pragma unroll 4
                for (int d = 0; d < 32; d++) {
                    float qv[4], kk[4];
                    #pragma unroll
                    for (int i = 0; i < 4; i++) qv[i] = sm[OFF_Q + (n0 + i) * PITCH + h * 32 + d];
                    #pragma unroll
                    for (int j = 0; j < 4; j++) kk[j] = sm[OFF_KH + (m0 + j) * 33 + d];
                    #pragma unroll
                    for (int i = 0; i < 4; i++)
                        #pragma unroll
                        for (int j = 0; j < 4; j++) acc[i][j] += qv[i] * kk[j];
                }
                const float* bb = g_bias + ((size_t)(br * 6 + h) << 12);
                #pragma unroll
                for (int i = 0; i < 4; i++)
                    #pragma unroll
                    for (int j = 0; j < 4; j++)
                        sm[OFF_S + (n0 + i) * 65 + m0 + j] =
                            acc[i][j] + bb[(n0 + i) * 64 + m0 + j]
                            + sm[OFF_MSK + (n0 + i) * 65 + m0 + j];
            }
            __syncthreads();

            // ---- softmax over rows ----
            {
                const int wi = t >> 5, l = t & 31;
                #pragma unroll
                for (int rr = 0; rr < 8; rr++) {
                    int r = wi * 8 + rr;
                    float v0 = sm[OFF_S + r * 65 + l];
                    float v1 = sm[OFF_S + r * 65 + 32 + l];
                    float mx = fmaxf(v0, v1);
                    #pragma unroll
                    for (int o = 16; o > 0; o >>= 1)
                        mx = fmaxf(mx, __shfl_xor_sync(0xffffffffu, mx, o));
                    float e0 = __expf(v0 - mx), e1 = __expf(v1 - mx);
                    float s = e0 + e1;
                    #pragma unroll
                    for (int o = 16; o > 0; o >>= 1)
                        s += __shfl_xor_sync(0xffffffffu, s, o);
                    float inv = 1.0f / s;
                    sm[OFF_S + r * 65 + l]      = e0 * inv;
                    sm[OFF_S + r * 65 + 32 + l] = e1 * inv;
                }
            }
            __syncthreads();

            // ---- O_h = P @ V_h ----
            {
                const int n0 = tr * 4, d0 = tc * 2;
                float acc[4][2];
                #pragma unroll
                for (int i = 0; i < 4; i++) { acc[i][0] = 0.f; acc[i][1] = 0.f; }
                #pragma unroll 4
                for (int m = 0; m < 64; m++) {
                    float v0 = sm[OFF_VH + m * 33 + d0];
                    float v1 = sm[OFF_VH + m * 33 + d0 + 1];
                    #pragma unroll
                    for (int i = 0; i < 4; i++) {
                        float p = sm[OFF_S + (n0 + i) * 65 + m];
                        acc[i][0] += p * v0;
                        acc[i][1] += p * v1;
                    }
                }
                #pragma unroll
                for (int i = 0; i < 4; i++) {
                    sm[OFF_OH + (n0 + i) * 33 + d0]     = acc[i][0];
                    sm[OFF_OH + (n0 + i) * 33 + d0 + 1] = acc[i][1];
                }
            }
            __syncthreads();

            // ---- stage merge1 slice transposed: W1t[d][o] ----
            for (int i = t; i < 6144; i += NT) {
                int o = i >> 5, d = i & 31;
                sm[OFF_WST + d * 198 + o] = merge1_w[o * 384 + br * 192 + h * 32 + d];
            }
            __syncthreads();

            // ---- M += O_h @ W1t ----
            {
                const int n0 = tr * 4, o0 = tc * 12;
                float acc[4][12];
                #pragma unroll
                for (int i = 0; i < 4; i++)
                    #pragma unroll
                    for (int j = 0; j < 12; j++) acc[i][j] = 0.f;
                #pragma unroll 2
                for (int d = 0; d < 32; d++) {
                    float a[4];
                    #pragma unroll
                    for (int i = 0; i < 4; i++) a[i] = sm[OFF_OH + (n0 + i) * 33 + d];
                    #pragma unroll
                    for (int j = 0; j < 12; j++) {
                        float wv = sm[OFF_WST + d * 198 + o0 + j];
                        #pragma unroll
                        for (int i = 0; i < 4; i++) acc[i][j] += a[i] * wv;
                    }
                }
                #pragma unroll
                for (int i = 0; i < 4; i++)
                    #pragma unroll
                    for (int j = 0; j < 12; j++)
                        sm[OFF_M + (n0 + i) * PITCH + o0 + j] += acc[i][j];
            }
            __syncthreads();
        }  // heads
    }  // branches

    // ---- leaky relu in place ----
    for (int i = t; i < 12288; i += NT) {
        int n = i / 192, c = i - n * 192;
        float v = sm[OFF_M + n * PITCH + c];
        sm[OFF_M + n * PITCH + c] = v > 0.f ? v : 0.2f * v;
    }
    __syncthreads();

    // ---- T = M @ merge2^T + b2 (into A), then out = T @ proj^T + pb ----
    for (int stage = 0; stage < 2; ++stage) {
        const float* W = stage ? proj_w : merge2_w;
        const float* B = stage ? proj_b : merge2_b;
        const int src = stage ? OFF_A : OFF_M;
        for (int ch = 0; ch < 3; ++ch) {
            for (int i = t; i < 12288; i += NT) {
                int j = i / 192, c = i - j * 192;
                sm[OFF_WTF + c * 65 + j] = W[(ch * 64 + j) * 192 + c];
            }
            __syncthreads();
            {
                const int n0 = tr * 4, j0 = tc * 4;
                float acc[4][4];
                #pragma unroll
                for (int j = 0; j < 4; j++) {
                    float bv = B[ch * 64 + j0 + j];
                    #pragma unroll
                    for (int i = 0; i < 4; i++) acc[i][j] = bv;
                }
                #pragma unroll 4
                for (int c = 0; c < 192; c++) {
                    float av[4], wv[4];
                    #pragma unroll
                    for (int i = 0; i < 4; i++) av[i] = sm[src + (n0 + i) * PITCH + c];
                    #pragma unroll
                    for (int j = 0; j < 4; j++) wv[j] = sm[OFF_WTF + c * 65 + j0 + j];
                    #pragma unroll
                    for (int i = 0; i < 4; i++)
                        #pragma unroll
                        for (int j = 0; j < 4; j++) acc[i][j] += av[i] * wv[j];
                }
                if (stage == 0) {
                    #pragma unroll
                    for (int i = 0; i < 4; i++)
                        #pragma unroll
                        for (int j = 0; j < 4; j++)
                            sm[OFF_A + (n0 + i) * PITCH + ch * 64 + j0 + j] = acc[i][j];
                } else {
                    float* op = out + (size_t)w * 12288;
                    #pragma unroll
                    for (int i = 0; i < 4; i++) {
                        float4 v4 = make_float4(acc[i][0], acc[i][1], acc[i][2], acc[i][3]);
                        *reinterpret_cast<float4*>(&op[(n0 + i) * 192 + ch * 64 + j0]) = v4;
                    }
                }
            }
            __syncthreads();
        }
    }
}

extern "C" void kernel_launch(void* const* d_in, const int* in_sizes, int n_in,
                              void* d_out, int out_size) {
    const float* x        = (const float*)d_in[0];
    const float* y        = (const float*)d_in[1];
    const float* mask_x   = (const float*)d_in[2];
    const float* mask_y   = (const float*)d_in[3];
    const float* qkv_w    = (const float*)d_in[4];
    const float* qkv_b    = (const float*)d_in[5];
    const float* kv_w     = (const float*)d_in[6];
    const float* kv_b     = (const float*)d_in[7];
    const float* rpb_x    = (const float*)d_in[8];
    const float* rpb_y    = (const float*)d_in[9];
    const float* merge1_w = (const float*)d_in[10];
    const float* merge1_b = (const float*)d_in[11];
    const float* merge2_w = (const float*)d_in[12];
    const float* merge2_b = (const float*)d_in[13];
    const float* proj_w   = (const float*)d_in[14];
    const float* proj_b   = (const float*)d_in[15];
    const int*   rel_idx  = (const int*)d_in[16];
    float* out = (float*)d_out;

    cudaFuncSetAttribute(fused_attn_kernel,
                         cudaFuncAttributeMaxDynamicSharedMemorySize,
                         SMEM_FLOATS * 4);

    bias_pre_kernel<<<192, 256>>>(rpb_x, rpb_y, rel_idx);
    fused_attn_kernel<<<2048, NT, SMEM_FLOATS * 4>>>(
        x, y, mask_x, mask_y, qkv_w, qkv_b, kv_w, kv_b,
        merge1_w, merge1_b, merge2_w, merge2_b, proj_w, proj_b, out);
}

// round 2
// speedup vs baseline: 1.0018x; 1.0018x over previous
#include <cuda_runtime.h>

#define NT 256
#define PITCH 193

// SMEM layout (floats)
#define OFF_A   0          // 64x192 pitch 193: X, then Y, then merge2 output T
#define OFF_Q   12352      // full Q (scaled)
#define OFF_M   24704      // merge1 accumulator
#define OFF_KH  37056      // 64x32 pitch 33
#define OFF_VH  39168
#define OFF_S   41280      // 64x64 pitch 65
#define OFF_OH  45440      // 64x32 pitch 33
#define OFF_MSK 47552      // 64x64 pitch 65
#define OFF_WST 51712      // 6336 floats: per-head W stage (pitch 33 or 198)
#define SMEM_FLOATS 58048  // 232192 bytes
#define OFF_WTF OFF_KH     // final-phase Wt stage overlay (192x65 = 12480 floats)

__device__ float g_bias[2 * 6 * 64 * 64];

__global__ void bias_pre_kernel(const float* __restrict__ rpb_x,
                                const float* __restrict__ rpb_y,
                                const int* __restrict__ rel_idx) {
    int i = blockIdx.x * blockDim.x + threadIdx.x;
    if (i >= 2 * 6 * 4096) return;
    int br = i / (6 * 4096);
    int h  = (i / 4096) % 6;
    int nm = i & 4095;
    const float* tab = br ? rpb_y : rpb_x;
    g_bias[i] = tab[rel_idx[nm] * 6 + h];
}

__global__ void __launch_bounds__(NT, 1) fused_attn_kernel(
    const float* __restrict__ x, const float* __restrict__ y,
    const float* __restrict__ mask_x, const float* __restrict__ mask_y,
    const float* __restrict__ qkv_w, const float* __restrict__ qkv_b,
    const float* __restrict__ kv_w, const float* __restrict__ kv_b,
    const float* __restrict__ merge1_w, const float* __restrict__ merge1_b,
    const float* __restrict__ merge2_w, const float* __restrict__ merge2_b,
    const float* __restrict__ proj_w, const float* __restrict__ proj_b,
    float* __restrict__ out)
{
    extern __shared__ float sm[];
    const int t = threadIdx.x;
    const int w = blockIdx.x;
    const int tr = t >> 4, tc = t & 15;
    const float scale = 0.17677669529663687f;  // 32^-0.5

    // ---- load X; init M with merge1_b ----
    {
        const float* xp = x + (size_t)w * 12288;
        for (int i = t; i < 12288; i += NT) {
            int n = i / 192, c = i - n * 192;
            sm[OFF_A + n * PITCH + c] = xp[i];
            sm[OFF_M + n * PITCH + c] = merge1_b[c];
        }
    }
    __syncthreads();

    // ---- full Q = scale*(X @ Wq^T + bq), per-head slices ----
    for (int h = 0; h < 6; ++h) {
        for (int i = t; i < 6144; i += NT) {
            int d = i / 192, c = i - d * 192;
            sm[OFF_WST + c * 33 + d] = qkv_w[(h * 32 + d) * 192 + c];
        }
        __syncthreads();
        {
            const int n0 = tr * 4, d0 = tc * 2;
            float b0 = qkv_b[h * 32 + d0], b1 = qkv_b[h * 32 + d0 + 1];
            float acc[4][2];
            #pragma unroll
            for (int i = 0; i < 4; i++) { acc[i][0] = b0; acc[i][1] = b1; }
            #pragma unroll 4
            for (int c = 0; c < 192; c++) {
                float w0 = sm[OFF_WST + c * 33 + d0];
                float w1 = sm[OFF_WST + c * 33 + d0 + 1];
                #pragma unroll
                for (int i = 0; i < 4; i++) {
                    float av = sm[OFF_A + (n0 + i) * PITCH + c];
                    acc[i][0] += av * w0;
                    acc[i][1] += av * w1;
                }
            }
            #pragma unroll
            for (int i = 0; i < 4; i++) {
                sm[OFF_Q + (n0 + i) * PITCH + h * 32 + d0]     = acc[i][0] * scale;
                sm[OFF_Q + (n0 + i) * PITCH + h * 32 + d0 + 1] = acc[i][1] * scale;
            }
        }
        __syncthreads();
    }

    // ---- two branches: self (K,V from X via qkv_w) / cross (K,V from Y via kv_w) ----
    for (int br = 0; br < 2; ++br) {
        if (br == 1) {
            const float* yp = y + (size_t)w * 12288;
            for (int i = t; i < 12288; i += NT) {
                int n = i / 192, c = i - n * 192;
                sm[OFF_A + n * PITCH + c] = yp[i];
            }
        }
        {
            const float* mk = (br ? mask_y : mask_x) + (size_t)(w & 1023) * 4096;
            for (int i = t; i < 4096; i += NT)
                sm[OFF_MSK + (i >> 6) * 65 + (i & 63)] = mk[i];
        }
        __syncthreads();

        const float* Wsrc = br ? kv_w : qkv_w;
        const float* Bsrc = br ? kv_b : qkv_b;
        const int krow0 = br ? 0 : 192;
        const int vrow0 = br ? 192 : 384;

        for (int h = 0; h < 6; ++h) {
            // ---- K_h then V_h ----
            for (int pass = 0; pass < 2; ++pass) {
                const int row0 = (pass ? vrow0 : krow0) + h * 32;
                const int dst = pass ? OFF_VH : OFF_KH;
                for (int i = t; i < 6144; i += NT) {
                    int d = i / 192, c = i - d * 192;
                    sm[OFF_WST + c * 33 + d] = Wsrc[(row0 + d) * 192 + c];
                }
                __syncthreads();
                {
                    const int n0 = tr * 4, d0 = tc * 2;
                    float b0 = Bsrc[row0 + d0], b1 = Bsrc[row0 + d0 + 1];
                    float acc[4][2];
                    #pragma unroll
                    for (int i = 0; i < 4; i++) { acc[i][0] = b0; acc[i][1] = b1; }
                    #pragma unroll 4
                    for (int c = 0; c < 192; c++) {
                        float w0 = sm[OFF_WST + c * 33 + d0];
                        float w1 = sm[OFF_WST + c * 33 + d0 + 1];
                        #pragma unroll
                        for (int i = 0; i < 4; i++) {
                            float av = sm[OFF_A + (n0 + i) * PITCH + c];
                            acc[i][0] += av * w0;
                            acc[i][1] += av * w1;
                        }
                    }
                    #pragma unroll
                    for (int i = 0; i < 4; i++) {
                        sm[dst + (n0 + i) * 33 + d0]     = acc[i][0];
                        sm[dst + (n0 + i) * 33 + d0 + 1] = acc[i][1];
                    }
                }
                __syncthreads();
            }

            // ---- S = Q_h K_h^T + bias + mask ----
            {
                const int n0 = tr * 4, m0 = tc * 4;
                float acc[4][4];
                #pragma unroll
                for (int i = 0; i < 4; i++)
                    #pragma unroll
                    for (int j = 0; j < 4; j++) acc[i][j] = 0.f;
                #pragma unroll 4
                for (int d = 0; d < 32; d++) {
                    float qv[4], kk[4];
                    #pragma unroll
                    for (int i = 0; i < 4; i++) qv[i] = sm[OFF_Q + (n0 + i) * PITCH + h * 32 + d];
                    #pragma unroll
                    for (int j = 0; j < 4; j++) kk[j] = sm[OFF_KH + (m0 + j) * 33 + d];
                    #pragma unroll
                    for (int i = 0; i < 4; i++)
                        #pragma unroll
                        for (int j = 0; j < 4; j++) acc[i][j] += qv[i] * kk[j];
                }
                const float* bb = g_bias + ((size_t)(br * 6 + h) << 12);
                #pragma unroll
                for (int i = 0; i < 4; i++)
                    #pragma unroll
                    for (int j = 0; j < 4; j++)
                        sm[OFF_S + (n0 + i) * 65 + m0 + j] =
                            acc[i][j] + bb[(n0 + i) * 64 + m0 + j]
                            + sm[OFF_MSK + (n0 + i) * 65 + m0 + j];
            }
            __syncthreads();

            // ---- softmax over rows ----
            {
                const int wi = t >> 5, l = t & 31;
                #pragma unroll
                for (int rr = 0; rr < 8; rr++) {
                    int r = wi * 8 + rr;
                    float v0 = sm[OFF_S + r * 65 + l];
                    float v1 = sm[OFF_S + r * 65 + 32 + l];
                    float mx = fmaxf(v0, v1);
                    #pragma unroll
                    for (int o = 16; o > 0; o >>= 1)
                        mx = fmaxf(mx, __shfl_xor_sync(0xffffffffu, mx, o));
                    float e0 = __expf(v0 - mx), e1 = __expf(v1 - mx);
                    float s = e0 + e1;
                    #pragma unroll
                    for (int o = 16; o > 0; o >>= 1)
                        s += __shfl_xor_sync(0xffffffffu, s, o);
                    float inv = 1.0f / s;
                    sm[OFF_S + r * 65 + l]      = e0 * inv;
                    sm[OFF_S + r * 65 + 32 + l] = e1 * inv;
                }
            }
            __syncthreads();

            // ---- O_h = P @ V_h ----
            {
                const int n0 = tr * 4, d0 = tc * 2;
                float acc[4][2];
                #pragma unroll
                for (int i = 0; i < 4; i++) { acc[i][0] = 0.f; acc[i][1] = 0.f; }
                #pragma unroll 4
                for (int m = 0; m < 64; m++) {
                    float v0 = sm[OFF_VH + m * 33 + d0];
                    float v1 = sm[OFF_VH + m * 33 + d0 + 1];
                    #pragma unroll
                    for (int i = 0; i < 4; i++) {
                        float p = sm[OFF_S + (n0 + i) * 65 + m];
                        acc[i][0] += p * v0;
                        acc[i][1] += p * v1;
                    }
                }
                #pragma unroll
                for (int i = 0; i < 4; i++) {
                    sm[OFF_OH + (n0 + i) * 33 + d0]     = acc[i][0];
                    sm[OFF_OH + (n0 + i) * 33 + d0 + 1] = acc[i][1];
                }
            }
            __syncthreads();

            // ---- stage merge1 slice transposed: W1t[d][o] ----
            for (int i = t; i < 6144; i += NT) {
                int o = i >> 5, d = i & 31;
                sm[OFF_WST + d * 198 + o] = merge1_w[o * 384 + br * 192 + h * 32 + d];
            }
            __syncthreads();

            // ---- M += O_h @ W1t ----
            {
                const int n0 = tr * 4, o0 = tc * 12;
                float acc[4][12];
                #pragma unroll
                for (int i = 0; i < 4; i++)
                    #pragma unroll
                    for (int j = 0; j < 12; j++) acc[i][j] = 0.f;
                #pragma unroll 2
                for (int d = 0; d < 32; d++) {
                    float a[4];
                    #pragma unroll
                    for (int i = 0; i < 4; i++) a[i] = sm[OFF_OH + (n0 + i) * 33 + d];
                    #pragma unroll
                    for (int j = 0; j < 12; j++) {
                        float wv = sm[OFF_WST + d * 198 + o0 + j];
                        #pragma unroll
                        for (int i = 0; i < 4; i++) acc[i][j] += a[i] * wv;
                    }
                }
                #pragma unroll
                for (int i = 0; i < 4; i++)
                    #pragma unroll
                    for (int j = 0; j < 12; j++)
                        sm[OFF_M + (n0 + i) * PITCH + o0 + j] += acc[i][j];
            }
            __syncthreads();
        }  // heads
    }  // branches

    // ---- leaky relu in place ----
    for (int i = t; i < 12288; i += NT) {
        int n = i / 192, c = i - n * 192;
        float v = sm[OFF_M + n * PITCH + c];
        sm[OFF_M + n * PITCH + c] = v > 0.f ? v : 0.2f * v;
    }
    __syncthreads();

    // ---- T = M @ merge2^T + b2 (into A), then out = T @ proj^T + pb ----
    for (int stage = 0; stage < 2; ++stage) {
        const float* W = stage ? proj_w : merge2_w;
        const float* B = stage ? proj_b : merge2_b;
        const int src = stage ? OFF_A : OFF_M;
        for (int ch = 0; ch < 3; ++ch) {
            for (int i = t; i < 12288; i += NT) {
                int j = i / 192, c = i - j * 192;
                sm[OFF_WTF + c * 65 + j] = W[(ch * 64 + j) * 192 + c];
            }
            __syncthreads();
            {
                const int n0 = tr * 4, j0 = tc * 4;
                float acc[4][4];
                #pragma unroll
                for (int j = 0; j < 4; j++) {
                    float bv = B[ch * 64 + j0 + j];
                    #pragma unroll
                    for (int i = 0; i < 4; i++) acc[i][j] = bv;
                }
                #pragma unroll 4
                for (int c = 0; c < 192; c++) {
                    float av[4], wv[4];
                    #pragma unroll
                    for (int i = 0; i < 4; i++) av[i] = sm[src + (n0 + i) * PITCH + c];
                    #pragma unroll
                    for (int j = 0; j < 4; j++) wv[j] = sm[OFF_WTF + c * 65 + j0 + j];
                    #pragma unroll
                    for (int i = 0; i < 4; i++)
                        #pragma unroll
                        for (int j = 0; j < 4; j++) acc[i][j] += av[i] * wv[j];
                }
                if (stage == 0) {
                    #pragma unroll
                    for (int i = 0; i < 4; i++)
                        #pragma unroll
                        for (int j = 0; j < 4; j++)
                            sm[OFF_A + (n0 + i) * PITCH + ch * 64 + j0 + j] = acc[i][j];
                } else {
                    float* op = out + (size_t)w * 12288;
                    #pragma unroll
                    for (int i = 0; i < 4; i++) {
                        float4 v4 = make_float4(acc[i][0], acc[i][1], acc[i][2], acc[i][3]);
                        *reinterpret_cast<float4*>(&op[(n0 + i) * 192 + ch * 64 + j0]) = v4;
                    }
                }
            }
            __syncthreads();
        }
    }
}

extern "C" void kernel_launch(void* const* d_in, const int* in_sizes, int n_in,
                              void* d_out, int out_size) {
    const float* x        = (const float*)d_in[0];
    const float* y        = (const float*)d_in[1];
    const float* mask_x   = (const float*)d_in[2];
    const float* mask_y   = (const float*)d_in[3];
    const float* qkv_w    = (const float*)d_in[4];
    const float* qkv_b    = (const float*)d_in[5];
    const float* kv_w     = (const float*)d_in[6];
    const float* kv_b     = (const float*)d_in[7];
    const float* rpb_x    = (const float*)d_in[8];
    const float* rpb_y    = (const float*)d_in[9];
    const float* merge1_w = (const float*)d_in[10];
    const float* merge1_b = (const float*)d_in[11];
    const float* merge2_w = (const float*)d_in[12];
    const float* merge2_b = (const float*)d_in[13];
    const float* proj_w   = (const float*)d_in[14];
    const float* proj_b   = (const float*)d_in[15];
    const int*   rel_idx  = (const int*)d_in[16];
    float* out = (float*)d_out;

    cudaFuncSetAttribute(fused_attn_kernel,
                         cudaFuncAttributeMaxDynamicSharedMemorySize,
                         SMEM_FLOATS * 4);

    bias_pre_kernel<<<192, 256>>>(rpb_x, rpb_y, rel_idx);
    fused_attn_kernel<<<2048, NT, SMEM_FLOATS * 4>>>(
        x, y, mask_x, mask_y, qkv_w, qkv_b, kv_w, kv_b,
        merge1_w, merge1_b, merge2_w, merge2_b, proj_w, proj_b, out);
}

// round 3
// speedup vs baseline: 1.0019x; 1.0000x over previous
#include <cuda_runtime.h>

#define NT 256
#define PITCH 193

// SMEM layout (floats)
#define OFF_A   0          // 64x192 pitch 193: X, then Y, then merge2 output T
#define OFF_Q   12352      // full Q (scaled)
#define OFF_M   24704      // merge1 accumulator
#define OFF_KH  37056      // 64x32 pitch 33
#define OFF_VH  39168
#define OFF_S   41280      // 64x64 pitch 65
#define OFF_OH  45440      // 64x32 pitch 33
#define OFF_MSK 47552      // 64x64 pitch 65
#define OFF_WST 51712      // 6336 floats: per-head W stage (pitch 33 or 198)
#define SMEM_FLOATS 58048  // 232192 bytes
#define OFF_WTF OFF_KH     // final-phase Wt stage overlay (192x65 = 12480 floats)

__device__ float g_bias[2 * 6 * 64 * 64];

__global__ void bias_pre_kernel(const float* __restrict__ rpb_x,
                                const float* __restrict__ rpb_y,
                                const int* __restrict__ rel_idx) {
    int i = blockIdx.x * blockDim.x + threadIdx.x;
    if (i >= 2 * 6 * 4096) return;
    int br = i / (6 * 4096);
    int h  = (i / 4096) % 6;
    int nm = i & 4095;
    const float* tab = br ? rpb_y : rpb_x;
    g_bias[i] = tab[rel_idx[nm] * 6 + h];
}

__global__ void __launch_bounds__(NT, 1) fused_attn_kernel(
    const float* __restrict__ x, const float* __restrict__ y,
    const float* __restrict__ mask_x, const float* __restrict__ mask_y,
    const float* __restrict__ qkv_w, const float* __restrict__ qkv_b,
    const float* __restrict__ kv_w, const float* __restrict__ kv_b,
    const float* __restrict__ merge1_w, const float* __restrict__ merge1_b,
    const float* __restrict__ merge2_w, const float* __restrict__ merge2_b,
    const float* __restrict__ proj_w, const float* __restrict__ proj_b,
    float* __restrict__ out)
{
    extern __shared__ float sm[];
    const int t = threadIdx.x;
    const int w = blockIdx.x;
    const int tr = t >> 4, tc = t & 15;
    const float scale = 0.17677669529663687f;  // 32^-0.5

    // ---- load X; init M with merge1_b ----
    {
        const float* xp = x + (size_t)w * 12288;
        for (int i = t; i < 12288; i += NT) {
            int n = i / 192, c = i - n * 192;
            sm[OFF_A + n * PITCH + c] = xp[i];
            sm[OFF_M + n * PITCH + c] = merge1_b[c];
        }
    }
    __syncthreads();

    // ---- full Q = scale*(X @ Wq^T + bq), per-head slices ----
    for (int h = 0; h < 6; ++h) {
        for (int i = t; i < 6144; i += NT) {
            int d = i / 192, c = i - d * 192;
            sm[OFF_WST + c * 33 + d] = qkv_w[(h * 32 + d) * 192 + c];
        }
        __syncthreads();
        {
            const int n0 = tr * 4, d0 = tc * 2;
            float b0 = qkv_b[h * 32 + d0], b1 = qkv_b[h * 32 + d0 + 1];
            float acc[4][2];
            #pragma unroll
            for (int i = 0; i < 4; i++) { acc[i][0] = b0; acc[i][1] = b1; }
            #pragma unroll 4
            for (int c = 0; c < 192; c++) {
                float w0 = sm[OFF_WST + c * 33 + d0];
                float w1 = sm[OFF_WST + c * 33 + d0 + 1];
                #pragma unroll
                for (int i = 0; i < 4; i++) {
                    float av = sm[OFF_A + (n0 + i) * PITCH + c];
                    acc[i][0] += av * w0;
                    acc[i][1] += av * w1;
                }
            }
            #pragma unroll
            for (int i = 0; i < 4; i++) {
                sm[OFF_Q + (n0 + i) * PITCH + h * 32 + d0]     = acc[i][0] * scale;
                sm[OFF_Q + (n0 + i) * PITCH + h * 32 + d0 + 1] = acc[i][1] * scale;
            }
        }
        __syncthreads();
    }

    // ---- two branches: self (K,V from X via qkv_w) / cross (K,V from Y via kv_w) ----
    for (int br = 0; br < 2; ++br) {
        if (br == 1) {
            const float* yp = y + (size_t)w * 12288;
            for (int i = t; i < 12288; i += NT) {
                int n = i / 192, c = i - n * 192;
                sm[OFF_A + n * PITCH + c] = yp[i];
            }
        }
        {
            const float* mk = (br ? mask_y : mask_x) + (size_t)(w & 1023) * 4096;
            for (int i = t; i < 4096; i += NT)
                sm[OFF_MSK + (i >> 6) * 65 + (i & 63)] = mk[i];
        }
        __syncthreads();

        const float* Wsrc = br ? kv_w : qkv_w;
        const float* Bsrc = br ? kv_b : qkv_b;
        const int krow0 = br ? 0 : 192;
        const int vrow0 = br ? 192 : 384;

        for (int h = 0; h < 6; ++h) {
            // ---- K_h then V_h ----
            for (int pass = 0; pass < 2; ++pass) {
                const int row0 = (pass ? vrow0 : krow0) + h * 32;
                const int dst = pass ? OFF_VH : OFF_KH;
                for (int i = t; i < 6144; i += NT) {
                    int d = i / 192, c = i - d * 192;
                    sm[OFF_WST + c * 33 + d] = Wsrc[(row0 + d) * 192 + c];
                }
                __syncthreads();
                {
                    const int n0 = tr * 4, d0 = tc * 2;
                    float b0 = Bsrc[row0 + d0], b1 = Bsrc[row0 + d0 + 1];
                    float acc[4][2];
                    #pragma unroll
                    for (int i = 0; i < 4; i++) { acc[i][0] = b0; acc[i][1] = b1; }
                    #pragma unroll 4
                    for (int c = 0; c < 192; c++) {
                        float w0 = sm[OFF_WST + c * 33 + d0];
                        float w1 = sm[OFF_WST + c * 33 + d0 + 1];
                        #pragma unroll
                        for (int i = 0; i < 4; i++) {
                            float av = sm[OFF_A + (n0 + i) * PITCH + c];
                            acc[i][0] += av * w0;
                            acc[i][1] += av * w1;
                        }
                    }
                    #pragma unroll
                    for (int i = 0; i < 4; i++) {
                        sm[dst + (n0 + i) * 33 + d0]     = acc[i][0];
                        sm[dst + (n0 + i) * 33 + d0 + 1] = acc[i][1];
                    }
                }
                __syncthreads();
            }

            // ---- S = Q_h K_h^T + bias + mask ----
            {
                const int n0 = tr * 4, m0 = tc * 4;
                float acc[4][4];
                #pragma unroll
                for (int i = 0; i < 4; i++)
                    #pragma unroll
                    for (int j = 0; j < 4; j++) acc[i][j] = 0.f;
                #pragma unroll 4
                for (int d = 0; d < 32; d++) {
                    float qv[4], kk[4];
                    #pragma unroll
                    for (int i = 0; i < 4; i++) qv[i] = sm[OFF_Q + (n0 + i) * PITCH + h * 32 + d];
                    #pragma unroll
                    for (int j = 0; j < 4; j++) kk[j] = sm[OFF_KH + (m0 + j) * 33 + d];
                    #pragma unroll
                    for (int i = 0; i < 4; i++)
                        #pragma unroll
                        for (int j = 0; j < 4; j++) acc[i][j] += qv[i] * kk[j];
                }
                const float* bb = g_bias + ((size_t)(br * 6 + h) << 12);
                #pragma unroll
                for (int i = 0; i < 4; i++)
                    #pragma unroll
                    for (int j = 0; j < 4; j++)
                        sm[OFF_S + (n0 + i) * 65 + m0 + j] =
                            acc[i][j] + bb[(n0 + i) * 64 + m0 + j]
                            + sm[OFF_MSK + (n0 + i) * 65 + m0 + j];
            }
            __syncthreads();

            // ---- softmax over rows ----
            {
                const int wi = t >> 5, l = t & 31;
                #pragma unroll
                for (int rr = 0; rr < 8; rr++) {
                    int r = wi * 8 + rr;
                    float v0 = sm[OFF_S + r * 65 + l];
                    float v1 = sm[OFF_S + r * 65 + 32 + l];
                    float mx = fmaxf(v0, v1);
                    #pragma unroll
                    for (int o = 16; o > 0; o >>= 1)
                        mx = fmaxf(mx, __shfl_xor_sync(0xffffffffu, mx, o));
                    float e0 = __expf(v0 - mx), e1 = __expf(v1 - mx);
                    float s = e0 + e1;
                    #pragma unroll
                    for (int o = 16; o > 0; o >>= 1)
                        s += __shfl_xor_sync(0xffffffffu, s, o);
                    float inv = 1.0f / s;
                    sm[OFF_S + r * 65 + l]      = e0 * inv;
                    sm[OFF_S + r * 65 + 32 + l] = e1 * inv;
                }
            }
            __syncthreads();

            // ---- O_h = P @ V_h ----
            {
                const int n0 = tr * 4, d0 = tc * 2;
                float acc[4][2];
                #pragma unroll
                for (int i = 0; i < 4; i++) { acc[i][0] = 0.f; acc[i][1] = 0.f; }
                #pragma unroll 4
                for (int m = 0; m < 64; m++) {
                    float v0 = sm[OFF_VH + m * 33 + d0];
                    float v1 = sm[OFF_VH + m * 33 + d0 + 1];
                    #pragma unroll
                    for (int i = 0; i < 4; i++) {
                        float p = sm[OFF_S + (n0 + i) * 65 + m];
                        acc[i][0] += p * v0;
                        acc[i][1] += p * v1;
                    }
                }
                #pragma unroll
                for (int i = 0; i < 4; i++) {
                    sm[OFF_OH + (n0 + i) * 33 + d0]     = acc[i][0];
                    sm[OFF_OH + (n0 + i) * 33 + d0 + 1] = acc[i][1];
                }
            }
            __syncthreads();

            // ---- stage merge1 slice transposed: W1t[d][o] ----
            for (int i = t; i < 6144; i += NT) {
                int o = i >> 5, d = i & 31;
                sm[OFF_WST + d * 198 + o] = merge1_w[o * 384 + br * 192 + h * 32 + d];
            }
            __syncthreads();

            // ---- M += O_h @ W1t ----
            {
                const int n0 = tr * 4, o0 = tc * 12;
                float acc[4][12];
                #pragma unroll
                for (int i = 0; i < 4; i++)
                    #pragma unroll
                    for (int j = 0; j < 12; j++) acc[i][j] = 0.f;
                #pragma unroll 2
                for (int d = 0; d < 32; d++) {
                    float a[4];
                    #pragma unroll
                    for (int i = 0; i < 4; i++) a[i] = sm[OFF_OH + (n0 + i) * 33 + d];
                    #pragma unroll
                    for (int j = 0; j < 12; j++) {
                        float wv = sm[OFF_WST + d * 198 + o0 + j];
                        #pragma unroll
                        for (int i = 0; i < 4; i++) acc[i][j] += a[i] * wv;
                    }
                }
                #pragma unroll
                for (int i = 0; i < 4; i++)
                    #pragma unroll
                    for (int j = 0; j < 12; j++)
                        sm[OFF_M + (n0 + i) * PITCH + o0 + j] += acc[i][j];
            }
            __syncthreads();
        }  // heads
    }  // branches

    // ---- leaky relu in place ----
    for (int i = t; i < 12288; i += NT) {
        int n = i / 192, c = i - n * 192;
        float v = sm[OFF_M + n * PITCH + c];
        sm[OFF_M + n * PITCH + c] = v > 0.f ? v : 0.2f * v;
    }
    __syncthreads();

    // ---- T = M @ merge2^T + b2 (into A), then out = T @ proj^T + pb ----
    for (int stage = 0; stage < 2; ++stage) {
        const float* W = stage ? proj_w : merge2_w;
        const float* B = stage ? proj_b : merge2_b;
        const int src = stage ? OFF_A : OFF_M;
        for (int ch = 0; ch < 3; ++ch) {
            for (int i = t; i < 12288; i += NT) {
                int j = i / 192, c = i - j * 192;
                sm[OFF_WTF + c * 65 + j] = W[(ch * 64 + j) * 192 + c];
            }
            __syncthreads();
            {
                const int n0 = tr * 4, j0 = tc * 4;
                float acc[4][4];
                #pragma unroll
                for (int j = 0; j < 4; j++) {
                    float bv = B[ch * 64 + j0 + j];
                    #pragma unroll
                    for (int i = 0; i < 4; i++) acc[i][j] = bv;
                }
                #pragma unroll 4
                for (int c = 0; c < 192; c++) {
                    float av[4], wv[4];
                    #pragma unroll
                    for (int i = 0; i < 4; i++) av[i] = sm[src + (n0 + i) * PITCH + c];
                    #pragma unroll
                    for (int j = 0; j < 4; j++) wv[j] = sm[OFF_WTF + c * 65 + j0 + j];
                    #pragma unroll
                    for (int i = 0; i < 4; i++)
                        #pragma unroll
                        for (int j = 0; j < 4; j++) acc[i][j] += av[i] * wv[j];
                }
                if (stage == 0) {
                    #pragma unroll
                    for (int i = 0; i < 4; i++)
                        #pragma unroll
                        for (int j = 0; j < 4; j++)
                            sm[OFF_A + (n0 + i) * PITCH + ch * 64 + j0 + j] = acc[i][j];
                } else {
                    float* op = out + (size_t)w * 12288;
                    #pragma unroll
                    for (int i = 0; i < 4; i++) {
                        float4 v4 = make_float4(acc[i][0], acc[i][1], acc[i][2], acc[i][3]);
                        *reinterpret_cast<float4*>(&op[(n0 + i) * 192 + ch * 64 + j0]) = v4;
                    }
                }
            }
            __syncthreads();
        }
    }
}

extern "C" void kernel_launch(void* const* d_in, const int* in_sizes, int n_in,
                              void* d_out, int out_size) {
    const float* x        = (const float*)d_in[0];
    const float* y        = (const float*)d_in[1];
    const float* mask_x   = (const float*)d_in[2];
    const float* mask_y   = (const float*)d_in[3];
    const float* qkv_w    = (const float*)d_in[4];
    const float* qkv_b    = (const float*)d_in[5];
    const float* kv_w     = (const float*)d_in[6];
    const float* kv_b     = (const float*)d_in[7];
    const float* rpb_x    = (const float*)d_in[8];
    const float* rpb_y    = (const float*)d_in[9];
    const float* merge1_w = (const float*)d_in[10];
    const float* merge1_b = (const float*)d_in[11];
    const float* merge2_w = (const float*)d_in[12];
    const float* merge2_b = (const float*)d_in[13];
    const float* proj_w   = (const float*)d_in[14];
    const float* proj_b   = (const float*)d_in[15];
    const int*   rel_idx  = (const int*)d_in[16];
    float* out = (float*)d_out;

    cudaFuncSetAttribute(fused_attn_kernel,
                         cudaFuncAttributeMaxDynamicSharedMemorySize,
                         SMEM_FLOATS * 4);

    bias_pre_kernel<<<192, 256>>>(rpb_x, rpb_y, rel_idx);
    fused_attn_kernel<<<2048, NT, SMEM_FLOATS * 4>>>(
        x, y, mask_x, mask_y, qkv_w, qkv_b, kv_w, kv_b,
        merge1_w, merge1_b, merge2_w, merge2_b, proj_w, proj_b, out);
}